// round 8
// baseline (speedup 1.0000x reference)
#include <cuda_runtime.h>

// VanillaRNN fused persistent kernel, v6.
// B=1024, T=512, I=64, H=128, O=10.
//
// v5 (2 independent CTAs/SM) + BALANCED MIXED-ROW GRID:
// grid = 296 = 148*2 CTAs. Classic bid->SM placement is LUT[bid%148], so
// bids b and b+148 share an SM. Bids [0,136) process 4 batch rows; bids
// [136,296) process 3. Every SM hosts 7 rows (136 SMs) or 6 rows (12 SMs)
// instead of v5's 8/4 split -> critical-path FFMA2 floor 1536 -> 1344 cyc/step.
// 3-row CTAs skip row-3 accumulation via a CTA-uniform branch.
//
// Thread mapping (unchanged): g = warp*4 + (lane&3) in [0,32): column group,
// cols {g, g+32, g+64, g+96}; seg = lane>>2 in [0,8): 24-wide k-segment of
// the 192-wide concat(x_t, h_t). Butterfly reduction xor4/xor8/xor16,
// 14 shfl/thread; lane finalizes row 2*sb0+sb1, cols {g+64*sb2, +32}.
// Segment stride 28 floats: 8 bases tile all 32 banks -> conflict-free LDS.128.

#define MAXROWS 4
#define NTHREADS 256
#define HDIM 128
#define IDIM 64
#define TSTEPS 512
#define ODIM 10
#define SEGF 24
#define SEGP 28
#define RSTRIDE 228
#define N4CTAS 136           // bids [0,136) -> 4 rows; rest -> 3 rows
#define GRID 296

__device__ __forceinline__ unsigned long long ffma2(unsigned long long a,
                                                    unsigned long long b,
                                                    unsigned long long c) {
    unsigned long long d;
    asm("fma.rn.f32x2 %0, %1, %2, %3;" : "=l"(d) : "l"(a), "l"(b), "l"(c));
    return d;
}

__device__ __forceinline__ unsigned long long packf2(float lo, float hi) {
    return ((unsigned long long)__float_as_uint(hi) << 32) |
           (unsigned long long)__float_as_uint(lo);
}

__device__ __forceinline__ float sum2(unsigned long long a) {
    return __uint_as_float((unsigned)a) + __uint_as_float((unsigned)(a >> 32));
}

__device__ __forceinline__ float fast_tanh(float z) {
    float e = __expf(2.0f * z);
    return 1.0f - __fdividef(2.0f, e + 1.0f);
}

__device__ __forceinline__ int physk(int k) { return k + 4 * (k / SEGF); }

__device__ __forceinline__ float wpick(const float* __restrict__ W_hx,
                                       const float* __restrict__ W_hh,
                                       int o, int k) {
    return (k < IDIM) ? W_hx[o * IDIM + k] : W_hh[o * HDIM + (k - IDIM)];
}

// accumulate one row's 24-k segment for 4 cols
__device__ __forceinline__ void row_acc(const float* __restrict__ rowbase,
                                        int segoff,
                                        const unsigned long long w[4][12],
                                        float sv[4]) {
    const ulonglong2* pp = (const ulonglong2*)(rowbase + segoff);
    unsigned long long a0 = 0ull, a1 = 0ull, a2 = 0ull, a3 = 0ull;
#pragma unroll
    for (int i = 0; i < 6; i++) {
        ulonglong2 v = pp[i];
        a0 = ffma2(v.x, w[0][2 * i], a0);
        a1 = ffma2(v.x, w[1][2 * i], a1);
        a2 = ffma2(v.x, w[2][2 * i], a2);
        a3 = ffma2(v.x, w[3][2 * i], a3);
        a0 = ffma2(v.y, w[0][2 * i + 1], a0);
        a1 = ffma2(v.y, w[1][2 * i + 1], a1);
        a2 = ffma2(v.y, w[2][2 * i + 1], a2);
        a3 = ffma2(v.y, w[3][2 * i + 1], a3);
    }
    sv[0] = sum2(a0); sv[1] = sum2(a1); sv[2] = sum2(a2); sv[3] = sum2(a3);
}

__global__ void __launch_bounds__(NTHREADS, 2)
rnn_fused_kernel(const float* __restrict__ x,
                 const float* __restrict__ W_hx,
                 const float* __restrict__ W_hh,
                 const float* __restrict__ b_hh,
                 const float* __restrict__ W_ph,
                 const float* __restrict__ b_ph,
                 float* __restrict__ out) {
    __shared__ __align__(16) float buf[2][MAXROWS][RSTRIDE];

    const int tid  = threadIdx.x;
    const int lane = tid & 31;
    const int warp = tid >> 5;
    const int g    = warp * 4 + (lane & 3);   // col group 0..31
    const int seg  = lane >> 2;               // k-segment 0..7
    const int kb   = seg * SEGF;
    const int bid  = blockIdx.x;

    const bool four  = (bid < N4CTAS);
    const int myrows = four ? 4 : 3;
    const int b0r    = four ? bid * 4 : N4CTAS * 4 + (bid - N4CTAS) * 3;

    // ---- weights: 4 cols x 12 packed f32x2 (24 logical k per col) = 96 regs
    unsigned long long w[4][12];
#pragma unroll
    for (int c = 0; c < 4; c++) {
        const int o = g + 32 * c;
#pragma unroll
        for (int j = 0; j < 12; j++) {
            const int k0 = kb + 2 * j;
            w[c][j] = packf2(wpick(W_hx, W_hh, o, k0),
                             wpick(W_hx, W_hh, o, k0 + 1));
        }
    }

    const int sb0 = seg & 1, sb1 = (seg >> 1) & 1, sb2 = (seg >> 2) & 1;
    const int mstar = 2 * sb0 + sb1;          // row this lane finalizes
    const int of0 = g + 64 * sb2;             // its two output columns
    const int of1 = of0 + 32;
    const float bb0 = b_hh[of0];
    const float bb1 = b_hh[of1];
    const int ph0 = physk(IDIM + of0);
    const int ph1 = physk(IDIM + of1);
    const int segoff = seg * SEGP;

    // ---- zero both buffers (h0 = 0; row 3 slot exists even for 3-row CTAs)
    for (int i = tid; i < 2 * MAXROWS * RSTRIDE; i += NTHREADS)
        ((float*)buf)[i] = 0.0f;

    // ---- x loader: tid<64, row xr (clamped), float4 chunk c4
    const int xr  = (tid >> 4) & 3;
    const int xrc = (xr < myrows) ? xr : myrows - 1;   // clamp for 3-row CTAs
    const int c4  = (tid & 15) * 4;
    const int pc4 = c4 + 4 * (c4 / SEGF);
    const bool loader = (tid < 64);
    const float* xrow = x + (size_t)(b0r + xrc) * TSTEPS * IDIM;

    if (loader)
        *(float4*)&buf[0][xr][pc4] = *(const float4*)(xrow + c4);
    __syncthreads();

    int p = 0;
    for (int t = 0; t < TSTEPS; t++) {
        float4 xn;
        if (loader) {
            const int tn = (t + 1 < TSTEPS) ? t + 1 : TSTEPS - 1;
            xn = *(const float4*)(xrow + (size_t)tn * IDIM + c4);
        }

        const float* base0 = &buf[p][0][0];
        const bool low0 = (sb0 == 0);

        // ---- pair A: rows {0, 2}; stage-0 butterfly folded in (xor 4)
        float ra[4];
        {
            float sA[4], sB[4];
            row_acc(base0 + 0 * RSTRIDE, segoff, w, sA);
            row_acc(base0 + 2 * RSTRIDE, segoff, w, sB);
#pragma unroll
            for (int c = 0; c < 4; c++) {
                float send = low0 ? sB[c] : sA[c];
                float recv = __shfl_xor_sync(0xffffffffu, send, 4);
                ra[c] = (low0 ? sA[c] : sB[c]) + recv;
            }
        }
        // ---- pair B: rows {1, 3}; 3-row CTAs skip row 3 (CTA-uniform branch)
        float rb[4];
        {
            float sA[4], sB[4];
            row_acc(base0 + 1 * RSTRIDE, segoff, w, sA);
            if (four) {
                row_acc(base0 + 3 * RSTRIDE, segoff, w, sB);
            } else {
                sB[0] = sB[1] = sB[2] = sB[3] = 0.0f;
            }
#pragma unroll
            for (int c = 0; c < 4; c++) {
                float send = low0 ? sB[c] : sA[c];
                float recv = __shfl_xor_sync(0xffffffffu, send, 4);
                rb[c] = (low0 ? sA[c] : sB[c]) + recv;
            }
        }

        // ---- stage 1 (xor 8): rows 2 -> 1
        float rc[4];
        {
            const bool low = (sb1 == 0);
#pragma unroll
            for (int c = 0; c < 4; c++) {
                float send = low ? rb[c] : ra[c];
                float recv = __shfl_xor_sync(0xffffffffu, send, 8);
                rc[c] = (low ? ra[c] : rb[c]) + recv;
            }
        }
        // ---- stage 2 (xor 16): cols 4 -> 2
        float f0, f1;
        {
            const bool low = (sb2 == 0);
            float send0 = low ? rc[2] : rc[0];
            float send1 = low ? rc[3] : rc[1];
            float recv0 = __shfl_xor_sync(0xffffffffu, send0, 16);
            float recv1 = __shfl_xor_sync(0xffffffffu, send1, 16);
            f0 = (low ? rc[0] : rc[2]) + recv0;
            f1 = (low ? rc[1] : rc[3]) + recv1;
        }

        // ---- finalize: row mstar, cols of0, of1 (row-3 write harmless for 3-row)
        const int q = p ^ 1;
        buf[q][mstar][ph0] = fast_tanh(f0 + bb0);
        buf[q][mstar][ph1] = fast_tanh(f1 + bb1);

        if (loader) *(float4*)&buf[q][xr][pc4] = xn;

        __syncthreads();
        p = q;
    }

    // ---- final projection: out[b0r+m][j] = b_ph[j] + sum_k h[m][k]*W_ph[j][k]
    if (tid < myrows * ODIM) {
        const int m = tid / ODIM;
        const int j = tid % ODIM;
        float s = b_ph[j];
#pragma unroll 4
        for (int k = 0; k < HDIM; k++)
            s += buf[p][m][physk(IDIM + k)] * W_ph[j * HDIM + k];
        out[(size_t)(b0r + m) * ODIM + j] = s;
    }
}

extern "C" void kernel_launch(void* const* d_in, const int* in_sizes, int n_in,
                              void* d_out, int out_size) {
    const float* x    = (const float*)d_in[0];
    const float* W_hx = (const float*)d_in[1];
    const float* W_hh = (const float*)d_in[2];
    const float* b_hh = (const float*)d_in[3];
    const float* W_ph = (const float*)d_in[4];
    const float* b_ph = (const float*)d_in[5];
    float* out = (float*)d_out;

    rnn_fused_kernel<<<GRID, NTHREADS>>>(x, W_hx, W_hh, b_hh, W_ph, b_ph, out);
}